// round 1
// baseline (speedup 1.0000x reference)
#include <cuda_runtime.h>

// WideComponent: out[b] = emb_user[u[b]] + emb_item[i[b]] + emb_cat[c[b]]
//                       + cross_w[u[b]*D_CAT + c[b]]
//                       + cross_w[OFF_IC + i[b]*D_CAT + c[b]]
// D_USER=100000, D_ITEM=50000, D_CAT=1000, OFF_IC = D_USER*D_CAT = 100,000,000
// B = 16384. All indices fit in int32 (max ~150,050,999 < 2^31).

static constexpr int D_CAT  = 1000;
static constexpr int OFF_IC = 100000 * D_CAT;  // 100,000,000

__global__ void __launch_bounds__(256) wide_kernel(
    const int* __restrict__ user_id,
    const int* __restrict__ item_id,
    const int* __restrict__ category,
    const float* __restrict__ emb_user,
    const float* __restrict__ emb_item,
    const float* __restrict__ emb_cat,
    const float* __restrict__ cross_w,
    float* __restrict__ out,
    int n)
{
    int b = blockIdx.x * blockDim.x + threadIdx.x;
    if (b >= n) return;

    // Three index loads (independent, issued back-to-back)
    int u = __ldg(&user_id[b]);
    int i = __ldg(&item_id[b]);
    int c = __ldg(&category[b]);

    // Five gathers — all independent of each other; ptxas will front-batch
    // them so the DRAM latencies overlap (MLP ~4 effective; emb_cat is a
    // 4KB table and will be an L1/L2 hit).
    float wu = __ldg(&emb_user[u]);
    float wi = __ldg(&emb_item[i]);
    float wc = __ldg(&emb_cat[c]);
    float xu = __ldg(&cross_w[u * D_CAT + c]);
    float xi = __ldg(&cross_w[OFF_IC + i * D_CAT + c]);

    out[b] = wu + wi + wc + xu + xi;
}

extern "C" void kernel_launch(void* const* d_in, const int* in_sizes, int n_in,
                              void* d_out, int out_size)
{
    const int*   user_id  = (const int*)  d_in[0];
    const int*   item_id  = (const int*)  d_in[1];
    const int*   category = (const int*)  d_in[2];
    const float* emb_user = (const float*)d_in[3];
    const float* emb_item = (const float*)d_in[4];
    const float* emb_cat  = (const float*)d_in[5];
    const float* cross_w  = (const float*)d_in[6];
    float*       out      = (float*)d_out;

    int n = in_sizes[0];  // B = 16384
    int threads = 256;
    int blocks = (n + threads - 1) / threads;
    wide_kernel<<<blocks, threads>>>(user_id, item_id, category,
                                     emb_user, emb_item, emb_cat, cross_w,
                                     out, n);
}

// round 3
// speedup vs baseline: 1.0048x; 1.0048x over previous
#include <cuda_runtime.h>

// WideComponent: out[b] = emb_user[u[b]] + emb_item[i[b]] + emb_cat[c[b]]
//                       + cross_w[u[b]*D_CAT + c[b]]
//                       + cross_w[OFF_IC + i[b]*D_CAT + c[b]]
// D_USER=100000, D_ITEM=50000, D_CAT=1000, OFF_IC = 100,000,000. B = 16384.
//
// Latency-bound tiny kernel. Key change vs R1: launch 128 CTAs x 128 threads
// instead of 64 x 256 so the same 512 warps cover 128 SMs instead of 64 —
// halves per-SM L1tex queue contention and the multi-CTA completion spread.

static constexpr int D_CAT  = 1000;
static constexpr int OFF_IC = 100000 * D_CAT;  // 100,000,000

__global__ void __launch_bounds__(128) wide_kernel(
    const int* __restrict__ user_id,
    const int* __restrict__ item_id,
    const int* __restrict__ category,
    const float* __restrict__ emb_user,
    const float* __restrict__ emb_item,
    const float* __restrict__ emb_cat,
    const float* __restrict__ cross_w,
    float* __restrict__ out,
    int n)
{
    int b = blockIdx.x * blockDim.x + threadIdx.x;
    if (b >= n) return;

    // Three independent index loads (coalesced, L2-hot across replays)
    int u = __ldg(&user_id[b]);
    int i = __ldg(&item_id[b]);
    int c = __ldg(&category[b]);

    // Five independent gathers, front-batched by ptxas (MLP=5).
    float wu = __ldg(&emb_user[u]);
    float wi = __ldg(&emb_item[i]);
    float wc = __ldg(&emb_cat[c]);
    float xu = __ldg(&cross_w[u * D_CAT + c]);
    float xi = __ldg(&cross_w[OFF_IC + i * D_CAT + c]);

    out[b] = wu + wi + wc + xu + xi;
}

extern "C" void kernel_launch(void* const* d_in, const int* in_sizes, int n_in,
                              void* d_out, int out_size)
{
    const int*   user_id  = (const int*)  d_in[0];
    const int*   item_id  = (const int*)  d_in[1];
    const int*   category = (const int*)  d_in[2];
    const float* emb_user = (const float*)d_in[3];
    const float* emb_item = (const float*)d_in[4];
    const float* emb_cat  = (const float*)d_in[5];
    const float* cross_w  = (const float*)d_in[6];
    float*       out      = (float*)d_out;

    int n = in_sizes[0];  // B = 16384
    int threads = 128;    // 128 CTAs -> near-full SM coverage, single wave
    int blocks = (n + threads - 1) / threads;
    wide_kernel<<<blocks, threads>>>(user_id, item_id, category,
                                     emb_user, emb_item, emb_cat, cross_w,
                                     out, n);
}